// round 10
// baseline (speedup 1.0000x reference)
#include <cuda_runtime.h>
#include <cstdint>

#define N_DIM   64
#define C_DIM   64
#define HW_DIM  16384
#define BINS    32
#define TOTAL_ELEMS (N_DIM * C_DIM * HW_DIM)   // 67,108,864
#define TOTAL_V4    (TOTAL_ELEMS / 4)          // 16,777,216
#define OUT_SIZE    (N_DIM * C_DIM)            // 4096

#define MM_GRID    2368      // 148 * 16 — balanced waves
#define MM_THREADS 256
#define MM_SPAN    (MM_GRID * MM_THREADS)

#define HP_GRID    2368
#define HP_THREADS 256
#define UNITS      16384     // quarter-rows: 4096 elems = 1024 float4 each

// Per-block partial min/max + finalized results. All state is rewritten every
// launch (finalizer resets g_done), so graph replay is deterministic.
__device__ float g_pmin[MM_GRID];
__device__ float g_pmax[MM_GRID];
__device__ float g_xmin;
__device__ float g_scale;
__device__ unsigned int g_done;   // zero at load; reset by finalizer each launch

// Hardware tanh (MUFU.TANH, sm_75+): single-op, ~2^-11 rel accuracy.
__device__ __forceinline__ float htanh(float x) {
    float y;
    asm("tanh.approx.f32 %0, %1;" : "=f"(y) : "f"(x));
    return y;
}

__global__ void __launch_bounds__(MM_THREADS) minmax_kernel(const float4* __restrict__ x,
                                                            float* __restrict__ out) {
    // Zero the output (poisoned by harness; hpool accumulates atomically).
    if (blockIdx.x < OUT_SIZE / MM_THREADS)          // 16 blocks x 256
        out[blockIdx.x * MM_THREADS + threadIdx.x] = 0.f;

    float vmin =  3.402823466e38f;
    float vmax = -3.402823466e38f;

    int tid = blockIdx.x * MM_THREADS + threadIdx.x;
    const int FULL = TOTAL_V4 / MM_SPAN;   // 27
    int r = 0;
    for (; r + 4 <= FULL; r += 4) {
        float4 a = x[tid + (size_t)(r + 0) * MM_SPAN];
        float4 b = x[tid + (size_t)(r + 1) * MM_SPAN];
        float4 c = x[tid + (size_t)(r + 2) * MM_SPAN];
        float4 d = x[tid + (size_t)(r + 3) * MM_SPAN];
        vmin = fminf(vmin, fminf(fminf(a.x, a.y), fminf(a.z, a.w)));
        vmax = fmaxf(vmax, fmaxf(fmaxf(a.x, a.y), fmaxf(a.z, a.w)));
        vmin = fminf(vmin, fminf(fminf(b.x, b.y), fminf(b.z, b.w)));
        vmax = fmaxf(vmax, fmaxf(fmaxf(b.x, b.y), fmaxf(b.z, b.w)));
        vmin = fminf(vmin, fminf(fminf(c.x, c.y), fminf(c.z, c.w)));
        vmax = fmaxf(vmax, fmaxf(fmaxf(c.x, c.y), fmaxf(c.z, c.w)));
        vmin = fminf(vmin, fminf(fminf(d.x, d.y), fminf(d.z, d.w)));
        vmax = fmaxf(vmax, fmaxf(fmaxf(d.x, d.y), fmaxf(d.z, d.w)));
    }
    for (; r < FULL; r++) {
        float4 a = x[tid + (size_t)r * MM_SPAN];
        vmin = fminf(vmin, fminf(fminf(a.x, a.y), fminf(a.z, a.w)));
        vmax = fmaxf(vmax, fmaxf(fmaxf(a.x, a.y), fmaxf(a.z, a.w)));
    }
    int idx = tid + FULL * MM_SPAN;        // ragged tail
    if (idx < TOTAL_V4) {
        float4 a = x[idx];
        vmin = fminf(vmin, fminf(fminf(a.x, a.y), fminf(a.z, a.w)));
        vmax = fmaxf(vmax, fmaxf(fmaxf(a.x, a.y), fmaxf(a.z, a.w)));
    }

    // warp reduce
    #pragma unroll
    for (int off = 16; off > 0; off >>= 1) {
        vmin = fminf(vmin, __shfl_xor_sync(0xFFFFFFFFu, vmin, off));
        vmax = fmaxf(vmax, __shfl_xor_sync(0xFFFFFFFFu, vmax, off));
    }
    __shared__ float smin[8], smax[8];
    __shared__ int s_last;
    int wid  = threadIdx.x >> 5;
    int lane = threadIdx.x & 31;
    if (lane == 0) { smin[wid] = vmin; smax[wid] = vmax; }
    __syncthreads();
    if (threadIdx.x == 0) {
        float bmin = smin[0], bmax = smax[0];
        #pragma unroll
        for (int w = 1; w < 8; w++) {
            bmin = fminf(bmin, smin[w]);
            bmax = fmaxf(bmax, smax[w]);
        }
        g_pmin[blockIdx.x] = bmin;
        g_pmax[blockIdx.x] = bmax;
        __threadfence();
        unsigned int v = atomicAdd(&g_done, 1u);
        s_last = (v == MM_GRID - 1) ? 1 : 0;
    }
    __syncthreads();

    // Last-arriving block finalizes: reduce all partials -> g_xmin/g_scale.
    if (s_last) {
        __threadfence();   // acquire: all partial writes visible
        float fmin =  3.402823466e38f;
        float fmax = -3.402823466e38f;
        for (int i = threadIdx.x; i < MM_GRID; i += MM_THREADS) {
            fmin = fminf(fmin, g_pmin[i]);
            fmax = fmaxf(fmax, g_pmax[i]);
        }
        #pragma unroll
        for (int off = 16; off > 0; off >>= 1) {
            fmin = fminf(fmin, __shfl_xor_sync(0xFFFFFFFFu, fmin, off));
            fmax = fmaxf(fmax, __shfl_xor_sync(0xFFFFFFFFu, fmax, off));
        }
        if (lane == 0) { smin[wid] = fmin; smax[wid] = fmax; }
        __syncthreads();
        if (threadIdx.x == 0) {
            float m0 = smin[0], m1 = smax[0];
            #pragma unroll
            for (int w = 1; w < 8; w++) {
                m0 = fminf(m0, smin[w]);
                m1 = fmaxf(m1, smax[w]);
            }
            float range = m1 - m0;
            g_xmin  = m0;
            g_scale = (range > 0.f) ? ((float)BINS / range) : 0.f;
            g_done  = 0;          // reset for next replay
            __threadfence();
        }
    }
}

__device__ __forceinline__ float proc4(float4 v, float xmin, float scale, float cw) {
    float acc = 0.f;
    #pragma unroll
    for (int j = 0; j < 4; j++) {
        float vv = (j == 0) ? v.x : (j == 1) ? v.y : (j == 2) ? v.z : v.w;
        float t  = htanh(vv);
        int b    = (int)((vv - xmin) * scale);
        b        = min(b, BINS - 1);
        float w  = __shfl_sync(0xFFFFFFFFu, cw, b);
        acc      = fmaf(t, w, acc);
    }
    return acc;
}

// Grid-stride over 16384 quarter-row units (1024 float4 = 4 per thread, MLP 4).
// Each unit lies entirely in one row; per-thread partial is REDG-added to out.
__global__ void __launch_bounds__(HP_THREADS) hpool_kernel(
    const float* __restrict__ x,
    const float* __restrict__ coeff,
    float* __restrict__ out)
{
    int tid  = threadIdx.x;
    int lane = tid & 31;

    float xmin  = g_xmin;
    float scale = g_scale;

    const float4* xv = (const float4*)x;

    for (int j = blockIdx.x; j < UNITS; j += HP_GRID) {
        int row = j >> 2;                       // (n*C + c)
        int c   = row & (C_DIM - 1);
        float cw = coeff[(c << 5) | lane];      // L1-resident 8KB table

        const float4* p = xv + (size_t)j * 1024;
        float4 v0 = p[tid];
        float4 v1 = p[tid + 256];
        float4 v2 = p[tid + 512];
        float4 v3 = p[tid + 768];

        float acc = proc4(v0, xmin, scale, cw)
                  + proc4(v1, xmin, scale, cw)
                  + proc4(v2, xmin, scale, cw)
                  + proc4(v3, xmin, scale, cw);

        atomicAdd(&out[row], acc);              // REDG.ADD.F32, L2-resident
    }
}

extern "C" void kernel_launch(void* const* d_in, const int* in_sizes, int n_in,
                              void* d_out, int out_size) {
    const float* x     = (const float*)d_in[0];
    const float* coeff = (const float*)d_in[1];
    float* out         = (float*)d_out;

    minmax_kernel<<<MM_GRID, MM_THREADS>>>((const float4*)x, out);
    hpool_kernel<<<HP_GRID, HP_THREADS>>>(x, coeff, out);
}